// round 15
// baseline (speedup 1.0000x reference)
#include <cuda_runtime.h>

#define T_STEPS 512
#define IN      9
#define INP     10      // padded (even) x width
#define HID     56
#define G4      224     // 4*HID
#define BB      14      // batches per CTA
#define NT      256     // threads per CTA

typedef unsigned long long u64;

__device__ __forceinline__ u64 pack2(float lo, float hi) {
    u64 r;
    asm("mov.b64 %0, {%1, %2};" : "=l"(r) : "f"(lo), "f"(hi));
    return r;
}

__device__ __forceinline__ void fma2(u64& acc, u64 a, u64 b) {
    asm("fma.rn.f32x2 %0, %1, %2, %3;" : "=l"(acc) : "l"(a), "l"(b), "l"(acc));
}

__device__ __forceinline__ float hsum2(u64 a, u64 b) {
    u64 s;
    asm("add.rn.f32x2 %0, %1, %2;" : "=l"(s) : "l"(a), "l"(b));
    float lo, hi;
    asm("mov.b64 {%0, %1}, %2;" : "=f"(lo), "=f"(hi) : "l"(s));
    return lo + hi;
}

// hardware tanh (MUFU.TANH)
__device__ __forceinline__ float tanh_hw(float x) {
    float y;
    asm("tanh.approx.f32 %0, %1;" : "=f"(y) : "f"(x));
    return y;
}
__device__ __forceinline__ float sigmoid_hw(float x) {
    return fmaf(0.5f, tanh_hw(0.5f * x), 0.5f);
}

__global__ void __launch_bounds__(NT, 1)
lstm_fused_kernel(const float* __restrict__ x,
                  const float* __restrict__ w_ih0, const float* __restrict__ w_hh0,
                  const float* __restrict__ b_ih0, const float* __restrict__ b_hh0,
                  const float* __restrict__ w_ih1, const float* __restrict__ w_hh1,
                  const float* __restrict__ b_ih1, const float* __restrict__ b_hh1,
                  const float* __restrict__ fc1_w, const float* __restrict__ fc1_b,
                  const float* __restrict__ fc2_w, const float* __restrict__ fc2_b,
                  float* __restrict__ out, int batch_total)
{
    __shared__ __align__(16) float xs[BB][INP];     // holds x(t+1) during gate phase
    __shared__ __align__(16) float h0s[BB][HID];
    __shared__ __align__(16) float h1s[BB][HID];
    __shared__ float gsh0[BB][G4];                  // gates for layer 0 (next step)
    __shared__ float gsh1[BB][G4];                  // gates for layer 1 (this step)

    const int tid = threadIdx.x;
    const int b0  = blockIdx.x * BB;
    const int nb  = min(BB, batch_total - b0);   // uniform across block; always even

    // ---- per-gate weights packed as f32x2 pairs in registers (threads 0..223) ----
    u64 wxp[INP / 2];          // 5
    u64 w0p[HID / 2];          // 28
    u64 wi1p[HID / 2];         // 28
    u64 w1p[HID / 2];          // 28
    u64 bias0p = 0, bias1p = 0;
    const int g = tid;
    if (tid < G4) {
        #pragma unroll
        for (int j = 0; j < IN / 2; j++)
            wxp[j] = pack2(w_ih0[g * IN + 2 * j], w_ih0[g * IN + 2 * j + 1]);
        wxp[4] = pack2(w_ih0[g * IN + 8], 0.0f);
        #pragma unroll
        for (int k = 0; k < HID / 2; k++) {
            w0p[k]  = pack2(w_hh0[g * HID + 2 * k], w_hh0[g * HID + 2 * k + 1]);
            wi1p[k] = pack2(w_ih1[g * HID + 2 * k], w_ih1[g * HID + 2 * k + 1]);
            w1p[k]  = pack2(w_hh1[g * HID + 2 * k], w_hh1[g * HID + 2 * k + 1]);
        }
        bias0p = pack2(b_ih0[g] + b_hh0[g], 0.0f);
        bias1p = pack2(b_ih1[g] + b_hh1[g], 0.0f);
    }

    // ---- cell state in registers: cell index = tid + it*NT -> (b, u) ----
    float c0r[4], c1r[4];
    #pragma unroll
    for (int it = 0; it < 4; it++) { c0r[it] = 0.0f; c1r[it] = 0.0f; }

    // zero h state + xs pad
    for (int idx = tid; idx < BB * HID; idx += NT) {
        h0s[idx / HID][idx % HID] = 0.0f;
        h1s[idx / HID][idx % HID] = 0.0f;
    }
    if (tid < BB * INP) xs[tid / INP][tid % INP] = 0.0f;
    __syncthreads();
    // stage x(t=0)
    if (tid < nb * IN) {
        int b = tid / IN, j = tid % IN;
        xs[b][j] = x[(size_t)(b0 + b) * T_STEPS * IN + j];
    }
    __syncthreads();

    // ======== prologue: gates0(0) = bias0 + W_ih0 x(0)  (h0 == 0) ========
    if (tid < G4) {
        #pragma unroll 1
        for (int b = 0; b < nb; b++) {
            u64 a00 = bias0p, a01 = pack2(0.0f, 0.0f);
            const u64* xp = reinterpret_cast<const u64*>(xs[b]);
            fma2(a00, wxp[0], xp[0]);
            fma2(a01, wxp[1], xp[1]);
            fma2(a00, wxp[2], xp[2]);
            fma2(a01, wxp[3], xp[3]);
            fma2(a00, wxp[4], xp[4]);
            gsh0[b][g] = hsum2(a00, a01);
        }
    }
    __syncthreads();

    #pragma unroll 1
    for (int t = 0; t < T_STEPS; t++) {
        // ======== cell phase: cell0(t)  +  cell1(t-1)  + stage x(t+1) ========
        #pragma unroll
        for (int it = 0; it < 4; it++) {
            int c = tid + it * NT;
            if (c < nb * HID) {
                int b = c / HID, u = c % HID;
                // layer-0 cell, step t
                {
                    float gi = sigmoid_hw(gsh0[b][u]);
                    float gf = sigmoid_hw(gsh0[b][HID + u]);
                    float gg = tanh_hw(gsh0[b][2 * HID + u]);
                    float go = sigmoid_hw(gsh0[b][3 * HID + u]);
                    float cc = gf * c0r[it] + gi * gg;
                    c0r[it] = cc;
                    h0s[b][u] = go * tanh_hw(cc);
                }
                // layer-1 cell, step t-1
                if (t > 0) {
                    float gi = sigmoid_hw(gsh1[b][u]);
                    float gf = sigmoid_hw(gsh1[b][HID + u]);
                    float gg = tanh_hw(gsh1[b][2 * HID + u]);
                    float go = sigmoid_hw(gsh1[b][3 * HID + u]);
                    float cc = gf * c1r[it] + gi * gg;
                    c1r[it] = cc;
                    h1s[b][u] = go * tanh_hw(cc);
                }
            }
        }
        if (t + 1 < T_STEPS && tid < nb * IN) {
            int b = tid / IN, j = tid % IN;
            xs[b][j] = x[(size_t)(b0 + b) * T_STEPS * IN + (size_t)(t + 1) * IN + j];
        }
        __syncthreads();

        // ======== merged gate phase, 2-batch interleaved ========
        // gates1(t)   = bias1 + W_ih1 h0(t) + W_hh1 h1(t-1)   -> gsh1
        // gates0(t+1) = bias0 + W_ih0 x(t+1) + W_hh0 h0(t)    -> gsh0
        if (tid < G4) {
            #pragma unroll 1
            for (int bp = 0; bp < nb; bp += 2) {
                const int b  = bp;
                const int b2 = bp + 1;
                const u64 Z = pack2(0.0f, 0.0f);
                u64 a10 = bias1p, a11 = Z, a00 = bias0p, a01 = Z;  // batch b
                u64 d10 = bias1p, d11 = Z, d00 = bias0p, d01 = Z;  // batch b2
                const u64* xpA = reinterpret_cast<const u64*>(xs[b]);
                const u64* xpB = reinterpret_cast<const u64*>(xs[b2]);
                fma2(a00, wxp[0], xpA[0]);  fma2(d00, wxp[0], xpB[0]);
                fma2(a01, wxp[1], xpA[1]);  fma2(d01, wxp[1], xpB[1]);
                fma2(a00, wxp[2], xpA[2]);  fma2(d00, wxp[2], xpB[2]);
                fma2(a01, wxp[3], xpA[3]);  fma2(d01, wxp[3], xpB[3]);
                fma2(a00, wxp[4], xpA[4]);  fma2(d00, wxp[4], xpB[4]);
                const ulonglong2* hp0A = reinterpret_cast<const ulonglong2*>(h0s[b]);
                const ulonglong2* hp0B = reinterpret_cast<const ulonglong2*>(h0s[b2]);
                const ulonglong2* hp1A = reinterpret_cast<const ulonglong2*>(h1s[b]);
                const ulonglong2* hp1B = reinterpret_cast<const ulonglong2*>(h1s[b2]);
                #pragma unroll
                for (int k = 0; k < HID / 4; k++) {
                    ulonglong2 h0A = hp0A[k];
                    ulonglong2 h0B = hp0B[k];
                    fma2(a10, wi1p[2 * k],     h0A.x);
                    fma2(a11, wi1p[2 * k + 1], h0A.y);
                    fma2(d10, wi1p[2 * k],     h0B.x);
                    fma2(d11, wi1p[2 * k + 1], h0B.y);
                    fma2(a00, w0p[2 * k],      h0A.x);
                    fma2(a01, w0p[2 * k + 1],  h0A.y);
                    fma2(d00, w0p[2 * k],      h0B.x);
                    fma2(d01, w0p[2 * k + 1],  h0B.y);
                    ulonglong2 h1A = hp1A[k];
                    ulonglong2 h1B = hp1B[k];
                    fma2(a10, w1p[2 * k],      h1A.x);
                    fma2(a11, w1p[2 * k + 1],  h1A.y);
                    fma2(d10, w1p[2 * k],      h1B.x);
                    fma2(d11, w1p[2 * k + 1],  h1B.y);
                }
                gsh1[b][g]  = hsum2(a10, a11);
                gsh1[b2][g] = hsum2(d10, d11);
                gsh0[b][g]  = hsum2(a00, a01);
                gsh0[b2][g] = hsum2(d00, d01);
            }
        }
        __syncthreads();
    }

    // ======== epilogue: cell1(T-1) ========
    #pragma unroll
    for (int it = 0; it < 4; it++) {
        int c = tid + it * NT;
        if (c < nb * HID) {
            int b = c / HID, u = c % HID;
            float gi = sigmoid_hw(gsh1[b][u]);
            float gf = sigmoid_hw(gsh1[b][HID + u]);
            float gg = tanh_hw(gsh1[b][2 * HID + u]);
            float go = sigmoid_hw(gsh1[b][3 * HID + u]);
            float cc = gf * c1r[it] + gi * gg;
            h1s[b][u] = go * tanh_hw(cc);
        }
    }
    __syncthreads();

    // ======== FC head on final h1 ========
    if (tid < nb) {
        int b = tid;
        float acc2 = fc2_b[0];
        #pragma unroll 1
        for (int j = 0; j < HID / 2; j++) {
            float a = fc1_b[j];
            #pragma unroll
            for (int k = 0; k < HID; k++)
                a += fc1_w[j * HID + k] * h1s[b][k];
            a = fmaxf(a, 0.0f);
            acc2 += a * fc2_w[j];
        }
        out[b0 + b] = acc2;
    }
}

extern "C" void kernel_launch(void* const* d_in, const int* in_sizes, int n_in,
                              void* d_out, int out_size)
{
    const float* x     = (const float*)d_in[0];
    const float* w_ih0 = (const float*)d_in[1];
    const float* w_hh0 = (const float*)d_in[2];
    const float* b_ih0 = (const float*)d_in[3];
    const float* b_hh0 = (const float*)d_in[4];
    const float* w_ih1 = (const float*)d_in[5];
    const float* w_hh1 = (const float*)d_in[6];
    const float* b_ih1 = (const float*)d_in[7];
    const float* b_hh1 = (const float*)d_in[8];
    const float* fc1_w = (const float*)d_in[9];
    const float* fc1_b = (const float*)d_in[10];
    const float* fc2_w = (const float*)d_in[11];
    const float* fc2_b = (const float*)d_in[12];

    int B = out_size;                    // 2048 outputs, one per batch row
    int grid = (B + BB - 1) / BB;        // 147 CTAs

    lstm_fused_kernel<<<grid, NT>>>(x, w_ih0, w_hh0, b_ih0, b_hh0,
                                    w_ih1, w_hh1, b_ih1, b_hh1,
                                    fc1_w, fc1_b, fc2_w, fc2_b,
                                    (float*)d_out, B);
}

// round 16
// speedup vs baseline: 1.0032x; 1.0032x over previous
#include <cuda_runtime.h>

#define T_STEPS 512
#define IN      9
#define INP     10      // padded (even) x width
#define HID     56
#define G4      224     // 4*HID
#define BB      14      // batches per CTA
#define NT      256     // threads per CTA

typedef unsigned long long u64;

__device__ __forceinline__ u64 pack2(float lo, float hi) {
    u64 r;
    asm("mov.b64 %0, {%1, %2};" : "=l"(r) : "f"(lo), "f"(hi));
    return r;
}

__device__ __forceinline__ void fma2(u64& acc, u64 a, u64 b) {
    asm("fma.rn.f32x2 %0, %1, %2, %3;" : "=l"(acc) : "l"(a), "l"(b), "l"(acc));
}

__device__ __forceinline__ float hsum2(u64 a, u64 b) {
    u64 s;
    asm("add.rn.f32x2 %0, %1, %2;" : "=l"(s) : "l"(a), "l"(b));
    float lo, hi;
    asm("mov.b64 {%0, %1}, %2;" : "=f"(lo), "=f"(hi) : "l"(s));
    return lo + hi;
}

// hardware tanh (MUFU.TANH)
__device__ __forceinline__ float tanh_hw(float x) {
    float y;
    asm("tanh.approx.f32 %0, %1;" : "=f"(y) : "f"(x));
    return y;
}
__device__ __forceinline__ float sigmoid_hw(float x) {
    return fmaf(0.5f, tanh_hw(0.5f * x), 0.5f);
}

__global__ void __launch_bounds__(NT, 1)
lstm_fused_kernel(const float* __restrict__ x,
                  const float* __restrict__ w_ih0, const float* __restrict__ w_hh0,
                  const float* __restrict__ b_ih0, const float* __restrict__ b_hh0,
                  const float* __restrict__ w_ih1, const float* __restrict__ w_hh1,
                  const float* __restrict__ b_ih1, const float* __restrict__ b_hh1,
                  const float* __restrict__ fc1_w, const float* __restrict__ fc1_b,
                  const float* __restrict__ fc2_w, const float* __restrict__ fc2_b,
                  float* __restrict__ out, int batch_total)
{
    __shared__ __align__(16) float xs[BB][INP];     // holds x(t+1) during gate phase
    __shared__ __align__(16) float h0s[BB][HID];
    __shared__ __align__(16) float h1s[BB][HID];
    __shared__ float gsh0[BB][G4];                  // gates for layer 0 (next step)
    __shared__ float gsh1[BB][G4];                  // gates for layer 1 (this step)

    const int tid = threadIdx.x;
    const int b0  = blockIdx.x * BB;
    const int nb  = min(BB, batch_total - b0);   // uniform across block; always even

    // ---- per-gate weights packed as f32x2 pairs in registers (threads 0..223) ----
    u64 wxp[INP / 2];          // 5
    u64 w0p[HID / 2];          // 28
    u64 wi1p[HID / 2];         // 28
    u64 w1p[HID / 2];          // 28
    u64 bias0p = 0, bias1p = 0;
    const int g = tid;
    if (tid < G4) {
        #pragma unroll
        for (int j = 0; j < IN / 2; j++)
            wxp[j] = pack2(w_ih0[g * IN + 2 * j], w_ih0[g * IN + 2 * j + 1]);
        wxp[4] = pack2(w_ih0[g * IN + 8], 0.0f);
        #pragma unroll
        for (int k = 0; k < HID / 2; k++) {
            w0p[k]  = pack2(w_hh0[g * HID + 2 * k], w_hh0[g * HID + 2 * k + 1]);
            wi1p[k] = pack2(w_ih1[g * HID + 2 * k], w_ih1[g * HID + 2 * k + 1]);
            w1p[k]  = pack2(w_hh1[g * HID + 2 * k], w_hh1[g * HID + 2 * k + 1]);
        }
        bias0p = pack2(b_ih0[g] + b_hh0[g], 0.0f);
        bias1p = pack2(b_ih1[g] + b_hh1[g], 0.0f);
    }

    // ---- cell state in registers: cell index = tid + it*NT -> (b, u) ----
    float c0r[4], c1r[4];
    #pragma unroll
    for (int it = 0; it < 4; it++) { c0r[it] = 0.0f; c1r[it] = 0.0f; }

    // zero h state + xs pad
    for (int idx = tid; idx < BB * HID; idx += NT) {
        h0s[idx / HID][idx % HID] = 0.0f;
        h1s[idx / HID][idx % HID] = 0.0f;
    }
    if (tid < BB * INP) xs[tid / INP][tid % INP] = 0.0f;
    __syncthreads();
    // stage x(t=0)
    if (tid < nb * IN) {
        int b = tid / IN, j = tid % IN;
        xs[b][j] = x[(size_t)(b0 + b) * T_STEPS * IN + j];
    }
    __syncthreads();

    // ======== prologue: gates0(0) = bias0 + W_ih0 x(0)  (h0 == 0) ========
    if (tid < G4) {
        #pragma unroll 1
        for (int b = 0; b < nb; b++) {
            u64 a00 = bias0p, a01 = pack2(0.0f, 0.0f);
            const u64* xp = reinterpret_cast<const u64*>(xs[b]);
            fma2(a00, wxp[0], xp[0]);
            fma2(a01, wxp[1], xp[1]);
            fma2(a00, wxp[2], xp[2]);
            fma2(a01, wxp[3], xp[3]);
            fma2(a00, wxp[4], xp[4]);
            gsh0[b][g] = hsum2(a00, a01);
        }
    }
    __syncthreads();

    #pragma unroll 1
    for (int t = 0; t < T_STEPS; t++) {
        // ======== cell phase: cell0(t)  +  cell1(t-1)  + stage x(t+1) ========
        #pragma unroll
        for (int it = 0; it < 4; it++) {
            int c = tid + it * NT;
            if (c < nb * HID) {
                int b = c / HID, u = c % HID;
                // layer-0 cell, step t
                {
                    float gi = sigmoid_hw(gsh0[b][u]);
                    float gf = sigmoid_hw(gsh0[b][HID + u]);
                    float gg = tanh_hw(gsh0[b][2 * HID + u]);
                    float go = sigmoid_hw(gsh0[b][3 * HID + u]);
                    float cc = gf * c0r[it] + gi * gg;
                    c0r[it] = cc;
                    h0s[b][u] = go * tanh_hw(cc);
                }
                // layer-1 cell, step t-1
                if (t > 0) {
                    float gi = sigmoid_hw(gsh1[b][u]);
                    float gf = sigmoid_hw(gsh1[b][HID + u]);
                    float gg = tanh_hw(gsh1[b][2 * HID + u]);
                    float go = sigmoid_hw(gsh1[b][3 * HID + u]);
                    float cc = gf * c1r[it] + gi * gg;
                    c1r[it] = cc;
                    h1s[b][u] = go * tanh_hw(cc);
                }
            }
        }
        if (t + 1 < T_STEPS && tid < nb * IN) {
            int b = tid / IN, j = tid % IN;
            xs[b][j] = x[(size_t)(b0 + b) * T_STEPS * IN + (size_t)(t + 1) * IN + j];
        }
        __syncthreads();

        // ======== merged gate phase, 2-batch interleaved ========
        // gates1(t)   = bias1 + W_ih1 h0(t) + W_hh1 h1(t-1)   -> gsh1
        // gates0(t+1) = bias0 + W_ih0 x(t+1) + W_hh0 h0(t)    -> gsh0
        if (tid < G4) {
            #pragma unroll 1
            for (int bp = 0; bp < nb; bp += 2) {
                const int b  = bp;
                const int b2 = bp + 1;
                const u64 Z = pack2(0.0f, 0.0f);
                u64 a10 = bias1p, a11 = Z, a00 = bias0p, a01 = Z;  // batch b
                u64 d10 = bias1p, d11 = Z, d00 = bias0p, d01 = Z;  // batch b2
                const u64* xpA = reinterpret_cast<const u64*>(xs[b]);
                const u64* xpB = reinterpret_cast<const u64*>(xs[b2]);
                fma2(a00, wxp[0], xpA[0]);  fma2(d00, wxp[0], xpB[0]);
                fma2(a01, wxp[1], xpA[1]);  fma2(d01, wxp[1], xpB[1]);
                fma2(a00, wxp[2], xpA[2]);  fma2(d00, wxp[2], xpB[2]);
                fma2(a01, wxp[3], xpA[3]);  fma2(d01, wxp[3], xpB[3]);
                fma2(a00, wxp[4], xpA[4]);  fma2(d00, wxp[4], xpB[4]);
                const ulonglong2* hp0A = reinterpret_cast<const ulonglong2*>(h0s[b]);
                const ulonglong2* hp0B = reinterpret_cast<const ulonglong2*>(h0s[b2]);
                const ulonglong2* hp1A = reinterpret_cast<const ulonglong2*>(h1s[b]);
                const ulonglong2* hp1B = reinterpret_cast<const ulonglong2*>(h1s[b2]);
                #pragma unroll
                for (int k = 0; k < HID / 4; k++) {
                    ulonglong2 h0A = hp0A[k];
                    ulonglong2 h0B = hp0B[k];
                    fma2(a10, wi1p[2 * k],     h0A.x);
                    fma2(a11, wi1p[2 * k + 1], h0A.y);
                    fma2(d10, wi1p[2 * k],     h0B.x);
                    fma2(d11, wi1p[2 * k + 1], h0B.y);
                    fma2(a00, w0p[2 * k],      h0A.x);
                    fma2(a01, w0p[2 * k + 1],  h0A.y);
                    fma2(d00, w0p[2 * k],      h0B.x);
                    fma2(d01, w0p[2 * k + 1],  h0B.y);
                    ulonglong2 h1A = hp1A[k];
                    ulonglong2 h1B = hp1B[k];
                    fma2(a10, w1p[2 * k],      h1A.x);
                    fma2(a11, w1p[2 * k + 1],  h1A.y);
                    fma2(d10, w1p[2 * k],      h1B.x);
                    fma2(d11, w1p[2 * k + 1],  h1B.y);
                }
                gsh1[b][g]  = hsum2(a10, a11);
                gsh1[b2][g] = hsum2(d10, d11);
                gsh0[b][g]  = hsum2(a00, a01);
                gsh0[b2][g] = hsum2(d00, d01);
            }
        }
        __syncthreads();
    }

    // ======== epilogue: cell1(T-1) ========
    #pragma unroll
    for (int it = 0; it < 4; it++) {
        int c = tid + it * NT;
        if (c < nb * HID) {
            int b = c / HID, u = c % HID;
            float gi = sigmoid_hw(gsh1[b][u]);
            float gf = sigmoid_hw(gsh1[b][HID + u]);
            float gg = tanh_hw(gsh1[b][2 * HID + u]);
            float go = sigmoid_hw(gsh1[b][3 * HID + u]);
            float cc = gf * c1r[it] + gi * gg;
            h1s[b][u] = go * tanh_hw(cc);
        }
    }
    __syncthreads();

    // ======== FC head on final h1 ========
    if (tid < nb) {
        int b = tid;
        float acc2 = fc2_b[0];
        #pragma unroll 1
        for (int j = 0; j < HID / 2; j++) {
            float a = fc1_b[j];
            #pragma unroll
            for (int k = 0; k < HID; k++)
                a += fc1_w[j * HID + k] * h1s[b][k];
            a = fmaxf(a, 0.0f);
            acc2 += a * fc2_w[j];
        }
        out[b0 + b] = acc2;
    }
}

extern "C" void kernel_launch(void* const* d_in, const int* in_sizes, int n_in,
                              void* d_out, int out_size)
{
    const float* x     = (const float*)d_in[0];
    const float* w_ih0 = (const float*)d_in[1];
    const float* w_hh0 = (const float*)d_in[2];
    const float* b_ih0 = (const float*)d_in[3];
    const float* b_hh0 = (const float*)d_in[4];
    const float* w_ih1 = (const float*)d_in[5];
    const float* w_hh1 = (const float*)d_in[6];
    const float* b_ih1 = (const float*)d_in[7];
    const float* b_hh1 = (const float*)d_in[8];
    const float* fc1_w = (const float*)d_in[9];
    const float* fc1_b = (const float*)d_in[10];
    const float* fc2_w = (const float*)d_in[11];
    const float* fc2_b = (const float*)d_in[12];

    int B = out_size;                    // 2048 outputs, one per batch row
    int grid = (B + BB - 1) / BB;        // 147 CTAs

    lstm_fused_kernel<<<grid, NT>>>(x, w_ih0, w_hh0, b_ih0, b_hh0,
                                    w_ih1, w_hh1, b_ih1, b_hh1,
                                    fc1_w, fc1_b, fc2_w, fc2_b,
                                    (float*)d_out, B);
}